// round 4
// baseline (speedup 1.0000x reference)
#include <cuda_runtime.h>
#include <cuda_bf16.h>
#include <cstdint>

#define N_TREES     15
#define DEPTH       3
#define INPUT_DIM   128
#define N_CLASSES   10
#define N_LEAVES    8
#define N_INTERNAL  7
#define PER_TREE    983          // 7*128 + 7 + 8*10
#define NODES       105
#define N_PAD       112          // 14 * 8
#define TILE_M      128
#define THREADS     128

// ---- smem byte offsets ----
#define OFF_MTAB    0            // 1200 floats = 4800 B
#define OFF_BIAS    4800         // 105 floats
#define OFF_AHI     5376         // 128x128 bf16 = 32768 B (swizzled)
#define OFF_ALO     38144        // 32768 B
#define OFF_BHI     70912        // 112x128 bf16 = 28672 B
#define OFF_BLO     99584        // 28672 B
#define SMEM_TOTAL  128256
#define Z_STRIDE    113          // odd -> conflict-free per-row reads

// bf16 mma: D += A(row-major m16k16) * B(col-major k16n8)
#define MMA16816(cc, a0, a1, a2, a3, b0, b1) \
    asm volatile("mma.sync.aligned.m16n8k16.row.col.f32.bf16.bf16.f32 " \
        "{%0,%1,%2,%3}, {%4,%5,%6,%7}, {%8,%9}, {%0,%1,%2,%3};" \
        : "+f"((cc)[0]), "+f"((cc)[1]), "+f"((cc)[2]), "+f"((cc)[3]) \
        : "r"(a0), "r"(a1), "r"(a2), "r"(a3), "r"(b0), "r"(b1))

// swizzled byte offset inside a [rows][128 bf16] tile:
//   row*256 + ((chunk ^ (row&7)) * 16) + within-chunk bytes
__device__ __forceinline__ uint32_t swz(int row, int chunk, int inb) {
    return (uint32_t)(row * 256 + (((chunk) ^ (row & 7)) << 4) + inb);
}

__global__ __launch_bounds__(THREADS)
void sdt_mma_kernel(const float* __restrict__ x,
                    const float* __restrict__ params,
                    float* __restrict__ out,
                    int batch)
{
    extern __shared__ char smem[];
    float* Msm = reinterpret_cast<float*>(smem + OFF_MTAB);
    float* bsm = reinterpret_cast<float*>(smem + OFF_BIAS);
    const int tid = threadIdx.x;

    // ---- zero B hi+lo regions (pads rows 105..111) ----
    for (int i = tid; i < (2 * 28672) / 16; i += THREADS)
        reinterpret_cast<uint4*>(smem + OFF_BHI)[i] = make_uint4(0, 0, 0, 0);

    // ---- stage A: x tile -> bf16 hi/lo, swizzled ----
    {
        const float4* xv = reinterpret_cast<const float4*>(x)
                         + (size_t)blockIdx.x * TILE_M * (INPUT_DIM / 4);
        for (int idx = tid; idx < TILE_M * (INPUT_DIM / 4); idx += THREADS) {
            int r  = idx >> 5;
            int c4 = idx & 31;
            float4 v = xv[idx];
            __nv_bfloat16 h0 = __float2bfloat16(v.x);
            __nv_bfloat16 h1 = __float2bfloat16(v.y);
            __nv_bfloat16 h2 = __float2bfloat16(v.z);
            __nv_bfloat16 h3 = __float2bfloat16(v.w);
            __nv_bfloat16 l0 = __float2bfloat16(v.x - __bfloat162float(h0));
            __nv_bfloat16 l1 = __float2bfloat16(v.y - __bfloat162float(h1));
            __nv_bfloat16 l2 = __float2bfloat16(v.z - __bfloat162float(h2));
            __nv_bfloat16 l3 = __float2bfloat16(v.w - __bfloat162float(h3));
            // cols c..c+3 live in chunk c4>>1, bytes (c4&1)*8 .. +7
            uint32_t base = swz(r, c4 >> 1, (c4 & 1) << 3);
            *reinterpret_cast<__nv_bfloat162*>(smem + OFF_AHI + base)     = __nv_bfloat162(h0, h1);
            *reinterpret_cast<__nv_bfloat162*>(smem + OFF_AHI + base + 4) = __nv_bfloat162(h2, h3);
            *reinterpret_cast<__nv_bfloat162*>(smem + OFF_ALO + base)     = __nv_bfloat162(l0, l1);
            *reinterpret_cast<__nv_bfloat162*>(smem + OFF_ALO + base + 4) = __nv_bfloat162(l2, l3);
        }
    }

    // ---- stage B: W (105 x 128) -> bf16 hi/lo, swizzled ----
    for (int idx = tid; idx < NODES * INPUT_DIM; idx += THREADS) {
        int row = idx >> 7;
        int col = idx & 127;
        int t = row / N_INTERNAL;
        int n = row - t * N_INTERNAL;
        float v = params[t * PER_TREE + n * INPUT_DIM + col];
        __nv_bfloat16 h = __float2bfloat16(v);
        __nv_bfloat16 l = __float2bfloat16(v - __bfloat162float(h));
        uint32_t o = swz(row, col >> 3, (col & 7) << 1);
        *reinterpret_cast<__nv_bfloat16*>(smem + OFF_BHI + o) = h;
        *reinterpret_cast<__nv_bfloat16*>(smem + OFF_BLO + o) = l;
    }

    // ---- bias ----
    for (int j = tid; j < NODES; j += THREADS) {
        int t = j / N_INTERNAL;
        int n = j - t * N_INTERNAL;
        bsm[j] = params[t * PER_TREE + N_INTERNAL * INPUT_DIM + n];
    }

    // ---- M[t][l][c] = softmax(tree_w)[t] * softmax(leaf_logits[t][l])[c] ----
    if (tid < N_TREES * N_LEAVES) {
        int t = tid / N_LEAVES;
        int l = tid - t * N_LEAVES;
        const float* twl = params + N_TREES * PER_TREE;
        float mx = twl[0];
        #pragma unroll
        for (int i = 1; i < N_TREES; ++i) mx = fmaxf(mx, twl[i]);
        float s = 0.f;
        #pragma unroll
        for (int i = 0; i < N_TREES; ++i) s += __expf(twl[i] - mx);
        float tw = __expf(twl[t] - mx) / s;

        const float* ll = params + t * PER_TREE + N_INTERNAL * INPUT_DIM + N_INTERNAL
                        + l * N_CLASSES;
        float m2 = ll[0];
        #pragma unroll
        for (int c = 1; c < N_CLASSES; ++c) m2 = fmaxf(m2, ll[c]);
        float e[N_CLASSES];
        float s2 = 0.f;
        #pragma unroll
        for (int c = 0; c < N_CLASSES; ++c) { e[c] = __expf(ll[c] - m2); s2 += e[c]; }
        float inv = tw / s2;
        #pragma unroll
        for (int c = 0; c < N_CLASSES; ++c)
            Msm[(t * N_LEAVES + l) * N_CLASSES + c] = e[c] * inv;
    }
    __syncthreads();

    // ================= main loop: 3-pass bf16-split HMMA =================
    const int lane = tid & 31;
    const int w    = tid >> 5;
    const int rsub = lane >> 2;          // 0..7
    const int qb   = (lane & 3) << 2;    // byte offset within 16B chunk

    float cc[2][14][4];
    #pragma unroll
    for (int mt = 0; mt < 2; ++mt)
        #pragma unroll
        for (int nt = 0; nt < 14; ++nt)
            #pragma unroll
            for (int i = 0; i < 4; ++i) cc[mt][nt][i] = 0.f;

    #pragma unroll 1
    for (int pass = 0; pass < 3; ++pass) {
        const char* Ab = smem + (pass < 2 ? OFF_AHI : OFF_ALO);
        const char* Bb = smem + (pass == 1 ? OFF_BLO : OFF_BHI);
        #pragma unroll
        for (int ks = 0; ks < 8; ++ks) {
            const int ch0 = ks * 2, ch1 = ks * 2 + 1;
            uint32_t a[2][4];
            #pragma unroll
            for (int mt = 0; mt < 2; ++mt) {
                int rl = w * 32 + mt * 16 + rsub;
                int rh = rl + 8;
                a[mt][0] = *reinterpret_cast<const uint32_t*>(Ab + swz(rl, ch0, qb));
                a[mt][1] = *reinterpret_cast<const uint32_t*>(Ab + swz(rh, ch0, qb));
                a[mt][2] = *reinterpret_cast<const uint32_t*>(Ab + swz(rl, ch1, qb));
                a[mt][3] = *reinterpret_cast<const uint32_t*>(Ab + swz(rh, ch1, qb));
            }
            #pragma unroll
            for (int nt = 0; nt < 14; ++nt) {
                int n = nt * 8 + rsub;
                uint32_t b0 = *reinterpret_cast<const uint32_t*>(Bb + swz(n, ch0, qb));
                uint32_t b1 = *reinterpret_cast<const uint32_t*>(Bb + swz(n, ch1, qb));
                MMA16816(cc[0][nt], a[0][0], a[0][1], a[0][2], a[0][3], b0, b1);
                MMA16816(cc[1][nt], a[1][0], a[1][1], a[1][2], a[1][3], b0, b1);
            }
        }
    }

    // ---- scatter accumulators to z tile in smem (overwrites A region) ----
    __syncthreads();
    float* zsm = reinterpret_cast<float*>(smem + OFF_AHI);
    #pragma unroll
    for (int mt = 0; mt < 2; ++mt) {
        int row = w * 32 + mt * 16 + rsub;
        #pragma unroll
        for (int nt = 0; nt < 14; ++nt) {
            int col = nt * 8 + ((lane & 3) << 1);
            zsm[row * Z_STRIDE + col]           = cc[mt][nt][0];
            zsm[row * Z_STRIDE + col + 1]       = cc[mt][nt][1];
            zsm[(row + 8) * Z_STRIDE + col]     = cc[mt][nt][2];
            zsm[(row + 8) * Z_STRIDE + col + 1] = cc[mt][nt][3];
        }
    }
    __syncthreads();

    // ---- per-row tree epilogue ----
    float acc[N_CLASSES];
    #pragma unroll
    for (int c = 0; c < N_CLASSES; ++c) acc[c] = 0.f;

    const float* zrow = zsm + tid * Z_STRIDE;
    #pragma unroll
    for (int t = 0; t < N_TREES; ++t) {
        float p_[N_INTERNAL], q_[N_INTERNAL];
        #pragma unroll
        for (int n = 0; n < N_INTERNAL; ++n) {
            float zz = zrow[t * N_INTERNAL + n] + bsm[t * N_INTERNAL + n];
            float e  = __expf(-zz);
            float pp = 1.f / (1.f + e);     // sigmoid(z)  -> right-branch
            p_[n] = pp;
            q_[n] = e * pp;                 // sigmoid(-z) -> left-branch
        }
        float tp[N_LEAVES];
        #pragma unroll
        for (int l = 0; l < N_LEAVES; ++l) {
            int node = l + N_INTERNAL;
            float prob = 1.f;
            #pragma unroll
            for (int d = 0; d < DEPTH; ++d) {
                int par = (node - 1) >> 1;
                prob *= (node & 1) ? q_[par] : p_[par];
                node = par;
            }
            tp[l] = prob;
        }
        const float* Mt = Msm + t * N_LEAVES * N_CLASSES;
        #pragma unroll
        for (int l = 0; l < N_LEAVES; ++l) {
            #pragma unroll
            for (int c = 0; c < N_CLASSES; ++c)
                acc[c] = fmaf(tp[l], Mt[l * N_CLASSES + c], acc[c]);
        }
    }

    // ---- repack outputs through smem for coalesced STG.128 ----
    __syncthreads();                      // z reads done; reuse region
    float* osm = reinterpret_cast<float*>(smem + OFF_AHI);
    #pragma unroll
    for (int c = 0; c < N_CLASSES; ++c) osm[tid * N_CLASSES + c] = acc[c];
    __syncthreads();

    {
        const size_t obase = (size_t)blockIdx.x * TILE_M * N_CLASSES;
        const uint4* osv = reinterpret_cast<const uint4*>(osm);
        uint4* og = reinterpret_cast<uint4*>(out + obase);
        const int tot = TILE_M * N_CLASSES / 4;   // 320
        for (int i = tid; i < tot; i += THREADS) og[i] = osv[i];
    }
}

extern "C" void kernel_launch(void* const* d_in, const int* in_sizes, int n_in,
                              void* d_out, int out_size)
{
    const float* x      = (const float*)d_in[0];
    const float* params = (const float*)d_in[1];
    float* out          = (float*)d_out;

    int batch = in_sizes[0] / INPUT_DIM;

    cudaFuncSetAttribute(sdt_mma_kernel,
                         cudaFuncAttributeMaxDynamicSharedMemorySize,
                         SMEM_TOTAL);

    int grid = (batch + TILE_M - 1) / TILE_M;
    sdt_mma_kernel<<<grid, THREADS, SMEM_TOTAL>>>(x, params, out, batch);
}

// round 5
// speedup vs baseline: 1.8094x; 1.8094x over previous
#include <cuda_runtime.h>
#include <cuda_bf16.h>
#include <cstdint>

#define N_TREES     15
#define DEPTH       3
#define INPUT_DIM   128
#define N_CLASSES   10
#define N_LEAVES    8
#define N_INTERNAL  7
#define PER_TREE    983          // 7*128 + 7 + 8*10
#define NODES       105
#define N_PAD       112          // 14 * 8
#define TILE_M      128
#define THREADS     256

// ---- smem byte offsets ----
#define OFF_MTAB    0            // 1200 floats = 4800 B
#define OFF_BIAS    4800         // 112 floats = 448 B
#define OFF_BHI     5376         // 112x128 bf16 swizzled = 28672 B
#define OFF_AHI     34048        // 128x128 bf16 swizzled = 32768 B
#define OFF_ALO     66816        // 32768 B (A_lo; later reused for B_lo, then z tile)
#define SMEM_TOTAL  99584
#define Z_STRIDE    113          // odd -> conflict-free per-row reads

#define B_BYTES     28672        // 112 rows * 256 B

// precomputed (setup kernel) converted weights, swizzled identically to smem tiles
__device__ __align__(16) unsigned char gBhi[B_BYTES];
__device__ __align__(16) unsigned char gBlo[B_BYTES];
__device__ float gBias[N_PAD];
__device__ float gMtab[N_TREES * N_LEAVES * N_CLASSES];

// bf16 mma: D += A(row-major m16k16) * B(col-major k16n8)
#define MMA16816(cc, a0, a1, a2, a3, b0, b1) \
    asm volatile("mma.sync.aligned.m16n8k16.row.col.f32.bf16.bf16.f32 " \
        "{%0,%1,%2,%3}, {%4,%5,%6,%7}, {%8,%9}, {%0,%1,%2,%3};" \
        : "+f"((cc)[0]), "+f"((cc)[1]), "+f"((cc)[2]), "+f"((cc)[3]) \
        : "r"(a0), "r"(a1), "r"(a2), "r"(a3), "r"(b0), "r"(b1))

#define LDSM_X4(r0, r1, r2, r3, addr) \
    asm volatile("ldmatrix.sync.aligned.m8n8.x4.shared.b16 {%0,%1,%2,%3}, [%4];" \
        : "=r"(r0), "=r"(r1), "=r"(r2), "=r"(r3) : "r"(addr))

// swizzled byte offset inside a [rows][128 bf16] tile:
//   row*256 + ((chunk ^ (row&7)) * 16) + within-chunk bytes
__device__ __host__ __forceinline__ uint32_t swz(int row, int chunk, int inb) {
    return (uint32_t)(row * 256 + (((chunk) ^ (row & 7)) << 4) + inb);
}

__device__ __forceinline__ uint32_t smem_u32(const void* p) {
    uint32_t a;
    asm("{ .reg .u64 t; cvta.to.shared.u64 t, %1; cvt.u32.u64 %0, t; }"
        : "=r"(a) : "l"(p));
    return a;
}

// ===================== setup kernel: convert W once =====================
__global__ void sdt_setup_kernel(const float* __restrict__ params)
{
    const int tid = threadIdx.x;   // 128 threads

    for (int idx = tid; idx < N_PAD * INPUT_DIM; idx += 128) {
        int row = idx >> 7;
        int col = idx & 127;
        float v = 0.f;
        if (row < NODES) {
            int t = row / N_INTERNAL;
            int n = row - t * N_INTERNAL;
            v = params[t * PER_TREE + n * INPUT_DIM + col];
        }
        __nv_bfloat16 h = __float2bfloat16(v);
        __nv_bfloat16 l = __float2bfloat16(v - __bfloat162float(h));
        uint32_t o = swz(row, col >> 3, (col & 7) << 1);
        *reinterpret_cast<__nv_bfloat16*>(gBhi + o) = h;
        *reinterpret_cast<__nv_bfloat16*>(gBlo + o) = l;
    }
    if (tid < N_PAD) {
        float v = 0.f;
        if (tid < NODES) {
            int t = tid / N_INTERNAL;
            int n = tid - t * N_INTERNAL;
            v = params[t * PER_TREE + N_INTERNAL * INPUT_DIM + n];
        }
        gBias[tid] = v;
    }
    if (tid < N_TREES * N_LEAVES) {
        int t = tid / N_LEAVES;
        int l = tid - t * N_LEAVES;
        const float* twl = params + N_TREES * PER_TREE;
        float mx = twl[0];
        #pragma unroll
        for (int i = 1; i < N_TREES; ++i) mx = fmaxf(mx, twl[i]);
        float s = 0.f;
        #pragma unroll
        for (int i = 0; i < N_TREES; ++i) s += __expf(twl[i] - mx);
        float tw = __expf(twl[t] - mx) / s;

        const float* ll = params + t * PER_TREE + N_INTERNAL * INPUT_DIM + N_INTERNAL
                        + l * N_CLASSES;
        float m2 = ll[0];
        #pragma unroll
        for (int c = 1; c < N_CLASSES; ++c) m2 = fmaxf(m2, ll[c]);
        float e[N_CLASSES];
        float s2 = 0.f;
        #pragma unroll
        for (int c = 0; c < N_CLASSES; ++c) { e[c] = __expf(ll[c] - m2); s2 += e[c]; }
        float inv = tw / s2;
        #pragma unroll
        for (int c = 0; c < N_CLASSES; ++c)
            gMtab[(t * N_LEAVES + l) * N_CLASSES + c] = e[c] * inv;
    }
}

// ===================== main kernel =====================
__global__ __launch_bounds__(THREADS, 2)
void sdt_mma_kernel(const float* __restrict__ x,
                    float* __restrict__ out,
                    int batch)
{
    extern __shared__ char smem[];
    const uint32_t sb = smem_u32(smem);
    const int tid  = threadIdx.x;
    const int lane = tid & 31;
    const int w    = tid >> 5;        // 0..7, warp owns rows w*16..w*16+15

    // ---- copy precomputed B_hi, Mtab, bias into smem ----
    {
        const uint4* src = reinterpret_cast<const uint4*>(gBhi);
        uint4* dst = reinterpret_cast<uint4*>(smem + OFF_BHI);
        #pragma unroll
        for (int i = 0; i < B_BYTES / 16 / THREADS; ++i)
            dst[tid + i * THREADS] = src[tid + i * THREADS];
    }
    {
        float* msm = reinterpret_cast<float*>(smem + OFF_MTAB);
        for (int i = tid; i < N_TREES * N_LEAVES * N_CLASSES; i += THREADS)
            msm[i] = gMtab[i];
        float* bsm = reinterpret_cast<float*>(smem + OFF_BIAS);
        if (tid < N_PAD) bsm[tid] = gBias[tid];
    }

    // ---- stage A: x tile -> bf16 hi/lo, swizzled ----
    {
        const float4* xv = reinterpret_cast<const float4*>(x)
                         + (size_t)blockIdx.x * TILE_M * (INPUT_DIM / 4);
        #pragma unroll
        for (int it = 0; it < TILE_M * (INPUT_DIM / 4) / THREADS; ++it) {
            int idx = tid + it * THREADS;
            int r  = idx >> 5;
            int c4 = idx & 31;
            float4 v = xv[idx];
            __nv_bfloat16 h0 = __float2bfloat16(v.x);
            __nv_bfloat16 h1 = __float2bfloat16(v.y);
            __nv_bfloat16 h2 = __float2bfloat16(v.z);
            __nv_bfloat16 h3 = __float2bfloat16(v.w);
            __nv_bfloat16 l0 = __float2bfloat16(v.x - __bfloat162float(h0));
            __nv_bfloat16 l1 = __float2bfloat16(v.y - __bfloat162float(h1));
            __nv_bfloat16 l2 = __float2bfloat16(v.z - __bfloat162float(h2));
            __nv_bfloat16 l3 = __float2bfloat16(v.w - __bfloat162float(h3));
            uint32_t base = swz(r, c4 >> 1, (c4 & 1) << 3);
            *reinterpret_cast<__nv_bfloat162*>(smem + OFF_AHI + base)     = __nv_bfloat162(h0, h1);
            *reinterpret_cast<__nv_bfloat162*>(smem + OFF_AHI + base + 4) = __nv_bfloat162(h2, h3);
            *reinterpret_cast<__nv_bfloat162*>(smem + OFF_ALO + base)     = __nv_bfloat162(l0, l1);
            *reinterpret_cast<__nv_bfloat162*>(smem + OFF_ALO + base + 4) = __nv_bfloat162(l2, l3);
        }
    }
    __syncthreads();

    // ================= 3-pass bf16-split HMMA mainloop =================
    // ldmatrix lane-address precompute.
    // A x4: m0=a0(rows 0-7,ch+0) m1=a1(rows 8-15,ch+0) m2=a2(rows 0-7,ch+1) m3=a3(rows 8-15,ch+1)
    const int arow  = w * 16 + ((lane >> 3) & 1) * 8 + (lane & 7);
    const int apar  = lane >> 4;            // 0 for m0/m1, 1 for m2/m3
    const uint32_t arow256 = arow * 256;
    const int arow7 = arow & 7;
    // B x4 group j: m0=(nt=2j,ch+0) m1=(nt=2j,ch+1) m2=(nt=2j+1,ch+0) m3=(nt=2j+1,ch+1)
    const int brow_local = ((lane >> 4) & 1) * 8 + (lane & 7);
    const int bpar  = (lane >> 3) & 1;

    float cc[14][4];
    #pragma unroll
    for (int nt = 0; nt < 14; ++nt)
        #pragma unroll
        for (int i = 0; i < 4; ++i) cc[nt][i] = 0.f;

    const uint32_t sBHI = sb + OFF_BHI;
    const uint32_t sAHI = sb + OFF_AHI;
    const uint32_t sALO = sb + OFF_ALO;

    #pragma unroll 1
    for (int pass = 0; pass < 3; ++pass) {
        const uint32_t Ab = (pass == 1) ? sALO : sAHI;   // Ah, Al, Ah
        const uint32_t Bb = (pass == 2) ? sALO : sBHI;   // Bh, Bh, Bl(in ALO)
        #pragma unroll
        for (int ks = 0; ks < 8; ++ks) {
            const int ch = ks * 2;
            uint32_t a0, a1, a2, a3;
            {
                int ach = ch + apar;
                LDSM_X4(a0, a1, a2, a3, Ab + arow256 + ((ach ^ arow7) << 4));
            }
            #pragma unroll
            for (int j = 0; j < 7; ++j) {
                int brow = j * 16 + brow_local;
                int bch  = ch + bpar;
                uint32_t b0A, b1A, b0B, b1B;
                LDSM_X4(b0A, b1A, b0B, b1B,
                        Bb + brow * 256 + ((bch ^ (brow & 7)) << 4));
                MMA16816(cc[2 * j],     a0, a1, a2, a3, b0A, b1A);
                MMA16816(cc[2 * j + 1], a0, a1, a2, a3, b0B, b1B);
            }
        }
        if (pass == 1) {
            // A_lo is consumed; overwrite its region with B_lo for pass 2
            __syncthreads();
            const uint4* src = reinterpret_cast<const uint4*>(gBlo);
            uint4* dst = reinterpret_cast<uint4*>(smem + OFF_ALO);
            #pragma unroll
            for (int i = 0; i < B_BYTES / 16 / THREADS; ++i)
                dst[tid + i * THREADS] = src[tid + i * THREADS];
            __syncthreads();
        }
    }

    // ---- scatter accumulators to z tile (reuse A_hi + A_lo regions) ----
    __syncthreads();
    float* zsm = reinterpret_cast<float*>(smem + OFF_AHI);
    {
        const int row = w * 16 + (lane >> 2);
        const int cbase = (lane & 3) << 1;
        #pragma unroll
        for (int nt = 0; nt < 14; ++nt) {
            int col = nt * 8 + cbase;
            zsm[row * Z_STRIDE + col]           = cc[nt][0];
            zsm[row * Z_STRIDE + col + 1]       = cc[nt][1];
            zsm[(row + 8) * Z_STRIDE + col]     = cc[nt][2];
            zsm[(row + 8) * Z_STRIDE + col + 1] = cc[nt][3];
        }
    }
    __syncthreads();

    // ---- per-row tree epilogue (threads 0..127 handle one row each) ----
    if (tid < TILE_M) {
        const float* Msm = reinterpret_cast<const float*>(smem + OFF_MTAB);
        const float* bsm = reinterpret_cast<const float*>(smem + OFF_BIAS);
        float* osm = reinterpret_cast<float*>(smem + OFF_BHI);  // B_hi dead

        float acc[N_CLASSES];
        #pragma unroll
        for (int c = 0; c < N_CLASSES; ++c) acc[c] = 0.f;

        const float* zrow = zsm + tid * Z_STRIDE;
        #pragma unroll
        for (int t = 0; t < N_TREES; ++t) {
            float p_[N_INTERNAL], q_[N_INTERNAL];
            #pragma unroll
            for (int n = 0; n < N_INTERNAL; ++n) {
                float zz = zrow[t * N_INTERNAL + n] + bsm[t * N_INTERNAL + n];
                float e  = __expf(-zz);
                float pp = 1.f / (1.f + e);
                p_[n] = pp;
                q_[n] = e * pp;
            }
            float tp[N_LEAVES];
            #pragma unroll
            for (int l = 0; l < N_LEAVES; ++l) {
                int node = l + N_INTERNAL;
                float prob = 1.f;
                #pragma unroll
                for (int d = 0; d < DEPTH; ++d) {
                    int par = (node - 1) >> 1;
                    prob *= (node & 1) ? q_[par] : p_[par];
                    node = par;
                }
                tp[l] = prob;
            }
            const float* Mt = Msm + t * N_LEAVES * N_CLASSES;
            #pragma unroll
            for (int l = 0; l < N_LEAVES; ++l) {
                #pragma unroll
                for (int c = 0; c < N_CLASSES; ++c)
                    acc[c] = fmaf(tp[l], Mt[l * N_CLASSES + c], acc[c]);
            }
        }
        #pragma unroll
        for (int c = 0; c < N_CLASSES; ++c)
            osm[tid * N_CLASSES + c] = acc[c];
    }
    __syncthreads();

    // ---- coalesced output copy ----
    {
        const float* osm = reinterpret_cast<const float*>(smem + OFF_BHI);
        const size_t obase = (size_t)blockIdx.x * TILE_M * N_CLASSES;
        const uint4* osv = reinterpret_cast<const uint4*>(osm);
        uint4* og = reinterpret_cast<uint4*>(out + obase);
        const int tot = TILE_M * N_CLASSES / 4;   // 320
        for (int i = tid; i < tot; i += THREADS) og[i] = osv[i];
    }
}

extern "C" void kernel_launch(void* const* d_in, const int* in_sizes, int n_in,
                              void* d_out, int out_size)
{
    const float* x      = (const float*)d_in[0];
    const float* params = (const float*)d_in[1];
    float* out          = (float*)d_out;

    int batch = in_sizes[0] / INPUT_DIM;

    cudaFuncSetAttribute(sdt_mma_kernel,
                         cudaFuncAttributeMaxDynamicSharedMemorySize,
                         SMEM_TOTAL);

    sdt_setup_kernel<<<1, 128>>>(params);

    int grid = (batch + TILE_M - 1) / TILE_M;
    sdt_mma_kernel<<<grid, THREADS, SMEM_TOTAL>>>(x, out, batch);
}